// round 3
// baseline (speedup 1.0000x reference)
#include <cuda_runtime.h>
#include <stdint.h>

#define NPROT 4096
#define IN_F  512
#define HALF  256
#define F     64
#define NW    128          // 4096 bits / 32 per row
#define ALPHA 0.2f
#define NEGBIG -3.4e38f

// ---------------- scratch (device globals; no allocation allowed) ----------
__device__ float    g_Wh1[NPROT * F];
__device__ float    g_Wh2[NPROT * F];
__device__ float    g_s1a[NPROT], g_s2a[NPROT];   // hop1: row score, col score
__device__ float    g_s1b[NPROT], g_s2b[NPROT];   // hop2
__device__ unsigned g_bits1[NPROT * NW];
__device__ unsigned g_bits2[NPROT * NW];
__device__ float    g_hp[NPROT * 2 * F];
__device__ float    g_cm1[F], g_cm2[F];
__device__ float    g_mean[2 * F], g_rstd[2 * F];

// ---------------- Wh = h @ [W1|W2], plus s-vectors ------------------------
__global__ void k_wh(const float* __restrict__ h, const float* __restrict__ W1,
                     const float* __restrict__ W2, const float* __restrict__ a)
{
    int i = blockIdx.x, t = threadIdx.x;          // 128 threads
    __shared__ float hrow[IN_F];
    __shared__ float red[256];
    for (int k = t; k < IN_F; k += 128) hrow[k] = h[i * IN_F + k];
    __syncthreads();

    const float* W  = (t < 64) ? W1 : W2;
    const float* hr = (t < 64) ? hrow : (hrow + HALF);
    int f = t & 63;
    float acc = 0.f;
#pragma unroll 8
    for (int k = 0; k < HALF; k++) acc = fmaf(hr[k], W[k * F + f], acc);
    if (t < 64) g_Wh1[i * F + f] = acc; else g_Wh2[i * F + f] = acc;

    red[t]       = acc * a[f];        // s1 partials (a[0:64])
    red[128 + t] = acc * a[64 + f];   // s2 partials (a[64:128])
    __syncthreads();
    for (int s = 32; s > 0; s >>= 1) {
        if ((t & 63) < s) { red[t] += red[t + s]; red[128 + t] += red[128 + t + s]; }
        __syncthreads();
    }
    if (t == 0)  { g_s1a[i] = red[0];  g_s2a[i] = red[128]; }
    if (t == 64) { g_s1b[i] = red[64]; g_s2b[i] = red[192]; }
}

// ---------------- column means of Wh (degree-0 fallback) -------------------
__global__ void k_colmean()
{
    int c = blockIdx.x;                            // 128 blocks
    const float* Wh = (c < 64) ? g_Wh1 : g_Wh2;
    int f = c & 63;
    float s = 0.f;
    for (int r = threadIdx.x; r < NPROT; r += 256) s += Wh[r * F + f];
    __shared__ float rs[256];
    rs[threadIdx.x] = s; __syncthreads();
    for (int st = 128; st > 0; st >>= 1) {
        if (threadIdx.x < st) rs[threadIdx.x] += rs[threadIdx.x + st];
        __syncthreads();
    }
    if (threadIdx.x == 0) {
        float m = rs[0] * (1.f / NPROT);
        if (c < 64) g_cm1[f] = m; else g_cm2[f] = m;
    }
}

// ---------------- bitpack adj ----------------------------------------------
__global__ void k_pack(const float* __restrict__ adj)
{
    int gt   = blockIdx.x * blockDim.x + threadIdx.x;
    int gw   = gt >> 5;                            // global warp = (row, word)
    int lane = threadIdx.x & 31;
    int row  = gw >> 7;
    int word = gw & 127;
    float v  = adj[(size_t)row * NPROT + word * 32 + lane];
    unsigned m = __ballot_sync(0xffffffffu, v > 0.f);
    if (lane == 0) g_bits1[row * NW + word] = m;
}

// ---------------- boolean adj^2 (OR of neighbor rows), diag cleared --------
__global__ void k_adj2()
{
    int i = blockIdx.x, t = threadIdx.x;           // 128 threads
    __shared__ unsigned short nbr[NPROT];
    __shared__ int cnt;
    if (t == 0) cnt = 0;
    __syncthreads();
    unsigned w = g_bits1[i * NW + t];
    int n = __popc(w);
    int base = n ? atomicAdd(&cnt, n) : 0;
    while (w) { int b = __ffs(w) - 1; w &= w - 1; nbr[base++] = (unsigned short)(t * 32 + b); }
    __syncthreads();
    unsigned acc = 0;
    int deg = cnt;
    for (int k = 0; k < deg; k++) acc |= g_bits1[(int)nbr[k] * NW + t];
    if (t == (i >> 5)) acc &= ~(1u << (i & 31));   // zero diagonal of adj2
    g_bits2[i * NW + t] = acc;
}

// ---------------- sparse masked softmax + aggregate ------------------------
__global__ void k_attn(int hop)
{
    const unsigned* __restrict__ bits = hop ? g_bits2 : g_bits1;
    const float* __restrict__ Wh      = hop ? g_Wh2   : g_Wh1;
    const float* __restrict__ s1      = hop ? g_s1b   : g_s1a;
    const float* __restrict__ s2      = hop ? g_s2b   : g_s2a;
    const float* __restrict__ cm      = hop ? g_cm2   : g_cm1;
    int colOff = hop ? 64 : 0;

    int i = blockIdx.x, t = threadIdx.x;           // 128 threads
    __shared__ unsigned short nbr[NPROT];
    __shared__ int cnt;
    __shared__ float red[128];
    __shared__ float dsh[2];
    if (t == 0) cnt = 0;
    __syncthreads();

    unsigned w = bits[i * NW + t];
    int n = __popc(w);
    int base = n ? atomicAdd(&cnt, n) : 0;
    while (w) { int b = __ffs(w) - 1; w &= w - 1; nbr[base++] = (unsigned short)(t * 32 + b); }
    __syncthreads();
    int deg = cnt;

    if (deg == 0) {                                 // uniform softmax == column mean
        if (t < 64) g_hp[i * 128 + colOff + t] = cm[t];
        return;
    }

    float s1i = s1[i];
    float m = NEGBIG;
    for (int k = t; k < deg; k += 128) {
        float e = s1i + s2[nbr[k]];
        e = (e > 0.f) ? e : ALPHA * e;
        m = fmaxf(m, e);
    }
    red[t] = m; __syncthreads();
    for (int s = 64; s > 0; s >>= 1) {
        if (t < s) red[t] = fmaxf(red[t], red[t + s]);
        __syncthreads();
    }
    m = red[0];
    __syncthreads();

    int g = t >> 6, f = t & 63;                    // 2 groups of 64 threads
    float num = 0.f, den = 0.f;
    for (int k = g; k < deg; k += 2) {
        int j = nbr[k];
        float e = s1i + s2[j];
        e = (e > 0.f) ? e : ALPHA * e;
        float wv = __expf(e - m);
        den += wv;
        num = fmaf(wv, Wh[j * F + f], num);
    }
    red[t] = num;
    if (f == 0) dsh[g] = den;
    __syncthreads();
    if (t < 64)
        g_hp[i * 128 + colOff + t] = (red[t] + red[t + 64]) / (dsh[0] + dsh[1]);
}

// ---------------- batchnorm stats -------------------------------------------
__global__ void k_bnstats()
{
    int c = blockIdx.x;                             // 128 blocks
    float s = 0.f, ss = 0.f;
    for (int r = threadIdx.x; r < NPROT; r += 256) {
        float v = g_hp[r * 128 + c];
        s += v; ss += v * v;
    }
    __shared__ float rs[256], rq[256];
    rs[threadIdx.x] = s; rq[threadIdx.x] = ss; __syncthreads();
    for (int st = 128; st > 0; st >>= 1) {
        if (threadIdx.x < st) {
            rs[threadIdx.x] += rs[threadIdx.x + st];
            rq[threadIdx.x] += rq[threadIdx.x + st];
        }
        __syncthreads();
    }
    if (threadIdx.x == 0) {
        float mean = rs[0] * (1.f / NPROT);
        float var  = rq[0] * (1.f / NPROT) - mean * mean;
        g_mean[c] = mean;
        g_rstd[c] = rsqrtf(var + 1e-5f);
    }
}

// ---------------- batchnorm apply + leakyrelu --------------------------------
__global__ void k_bnapply(const float* __restrict__ gamma,
                          const float* __restrict__ beta,
                          float* __restrict__ out)
{
    int idx = blockIdx.x * blockDim.x + threadIdx.x;   // 4096*128 elems
    int c = idx & 127;
    float v = g_hp[idx];
    float o = gamma[c] * (v - g_mean[c]) * g_rstd[c] + beta[c];
    out[idx] = (o > 0.f) ? o : ALPHA * o;
}

// ---------------- launch ------------------------------------------------------
extern "C" void kernel_launch(void* const* d_in, const int* in_sizes, int n_in,
                              void* d_out, int out_size)
{
    const float* h     = (const float*)d_in[0];
    const float* adj   = (const float*)d_in[1];
    const float* W1    = (const float*)d_in[2];
    const float* W2    = (const float*)d_in[3];
    const float* a     = (const float*)d_in[4];
    const float* gamma = (const float*)d_in[5];
    const float* beta  = (const float*)d_in[6];
    float* out = (float*)d_out;

    k_pack   <<<(NPROT * NW * 32) / 256, 256>>>(adj);
    k_wh     <<<NPROT, 128>>>(h, W1, W2, a);
    k_adj2   <<<NPROT, 128>>>();
    k_colmean<<<128, 256>>>();
    k_attn   <<<NPROT, 128>>>(0);
    k_attn   <<<NPROT, 128>>>(1);
    k_bnstats<<<128, 256>>>();
    k_bnapply<<<(NPROT * 128) / 256, 256>>>(gamma, beta, out);
}